// round 1
// baseline (speedup 1.0000x reference)
#include <cuda_runtime.h>

#define THREADS 256
#define NB      4
#define GRIDB   128
#define T_LEN   1000
#define CH      8
#define NCHUNK  125   // 1000 / 8

// shared memory layout (float offsets)
#define OFF_SW1 0                  // 24*256*4 = 24576 floats: LSTM1 combined weights, quad layout
#define OFF_SW2 24576              // 24*128*4 = 12288 floats: LSTM2 combined weights
#define OFF_B1  36864              // 256 : bias1 (b_ih1+b_hh1)
#define OFF_B2  37120              // 128 : bias2
#define OFF_V1  37248              // 4*96: per-batch [x(26) | h1(64) | pad(6)]
#define OFF_V2  37632              // 4*96: per-batch [h1(64) | h2(32)]
#define OFF_G1  38016              // 4*256 gates LSTM1
#define OFF_G2  39040              // 4*128 gates LSTM2
#define OFF_XS  39552              // 8*104 x staging
#define OFF_FC  40384              // 64 fc1 intermediate
#define SMEM_FLOATS 40448
#define SMEM_BYTES  (SMEM_FLOATS * 4)

typedef unsigned long long ull;

__device__ __forceinline__ ull fma2(ull a, ull b, ull c) {
    ull d;
    asm("fma.rn.f32x2 %0, %1, %2, %3;" : "=l"(d) : "l"(a), "l"(b), "l"(c));
    return d;
}
__device__ __forceinline__ float hadd(ull a) {
    return __uint_as_float((unsigned)a) + __uint_as_float((unsigned)(a >> 32));
}
__device__ __forceinline__ float sigf(float x) {
    return __fdividef(1.0f, 1.0f + __expf(-x));
}
__device__ __forceinline__ float tanh_(float x) {
    return 1.0f - __fdividef(2.0f, 1.0f + __expf(2.0f * x));
}

extern "C" __global__ void __launch_bounds__(THREADS, 1)
audiolstm_kernel(const float* __restrict__ x,
                 const float* __restrict__ w_ih1, const float* __restrict__ w_hh1,
                 const float* __restrict__ b_ih1, const float* __restrict__ b_hh1,
                 const float* __restrict__ w_ih2, const float* __restrict__ w_hh2,
                 const float* __restrict__ b_ih2, const float* __restrict__ b_hh2,
                 const float* __restrict__ w_fc1, const float* __restrict__ b_fc1,
                 const float* __restrict__ w_fc2, const float* __restrict__ b_fc2,
                 float* __restrict__ out)
{
    extern __shared__ float sm[];
    float* sw1  = sm + OFF_SW1;
    float* sw2  = sm + OFF_SW2;
    float* sb1  = sm + OFF_B1;
    float* sb2  = sm + OFF_B2;
    float* v1   = sm + OFF_V1;
    float* v2   = sm + OFF_V2;
    float* g1   = sm + OFF_G1;
    float* g2   = sm + OFF_G2;
    float* xs   = sm + OFF_XS;
    float* fc1s = sm + OFF_FC;

    const int tid = threadIdx.x;
    const int b0  = blockIdx.x * NB;

    // ---- stage LSTM1 combined weights: row j = [w_ih1[j][0..25] | w_hh1[j][0..63] | 0...]
    // quad layout sw1[(k>>2)*1024 + j*4 + (k&3)] -> thread j does conflict-free LDS.128
    for (int e = tid; e < 256 * 96; e += THREADS) {
        int j = e / 96, k = e - j * 96;
        float val = 0.f;
        if (k < 26)      val = w_ih1[j * 26 + k];
        else if (k < 90) val = w_hh1[j * 64 + (k - 26)];
        sw1[(k >> 2) * 1024 + j * 4 + (k & 3)] = val;
    }
    // ---- LSTM2 combined weights: row j = [w_ih2[j][0..63] | w_hh2[j][0..31]]
    for (int e = tid; e < 128 * 96; e += THREADS) {
        int j = e / 96, k = e - j * 96;
        float val = (k < 64) ? w_ih2[j * 64 + k] : w_hh2[j * 32 + (k - 64)];
        sw2[(k >> 2) * 512 + j * 4 + (k & 3)] = val;
    }
    sb1[tid] = b_ih1[tid] + b_hh1[tid];
    if (tid < 128) sb2[tid] = b_ih2[tid] + b_hh2[tid];
    for (int e = tid; e < 384; e += THREADS) { v1[e] = 0.f; v2[e] = 0.f; }

    // per-thread role constants
    const int  b2_ = tid >> 6, n2_ = tid & 63;    // LSTM1 state update
    const int  jr_ = tid & 127, p_ = tid >> 7;    // LSTM2 gate rows
    const int  b4_ = tid >> 5, n4_ = tid & 31;    // LSTM2 state update (tid<128)
    const int  xb_ = tid / 26, xi_ = tid - xb_ * 26;  // x loader (tid<104)
    const bool xthr = tid < 104;
    const float* xg = x + ((size_t)(b0 + (xthr ? xb_ : 0)) * 26 + xi_) * T_LEN;

    float c1s = 0.f;   // c1 for (b2_, n2_)
    float c2s = 0.f;   // c2 for (b4_, n4_) if tid<128

    float4 xa = make_float4(0.f, 0.f, 0.f, 0.f), xb2 = xa;
    if (xthr) { xa = *(const float4*)(xg); xb2 = *(const float4*)(xg + 4); }

    __syncthreads();

    const ull biasp1 = (ull)__float_as_uint(sb1[tid]);     // (bias, 0) packed
    const ull biasp2 = (ull)__float_as_uint(sb2[jr_]);

    #pragma unroll 1
    for (int c = 0; c < NCHUNK; ++c) {
        // stage current x chunk, prefetch next into registers
        if (xthr) {
            xs[0 * 104 + tid] = xa.x;  xs[1 * 104 + tid] = xa.y;
            xs[2 * 104 + tid] = xa.z;  xs[3 * 104 + tid] = xa.w;
            xs[4 * 104 + tid] = xb2.x; xs[5 * 104 + tid] = xb2.y;
            xs[6 * 104 + tid] = xb2.z; xs[7 * 104 + tid] = xb2.w;
            if (c < NCHUNK - 1) {
                xa  = *(const float4*)(xg + (c + 1) * CH);
                xb2 = *(const float4*)(xg + (c + 1) * CH + 4);
            }
        }
        #pragma unroll 1
        for (int tt = 0; tt < CH; ++tt) {
            __syncthreads();                       // S0: xs + h2 ready
            if (xthr) v1[xb_ * 96 + xi_] = xs[tt * 104 + tid];
            __syncthreads();                       // S1: v1 x-part ready

            // ---- phase 1: LSTM1 gates. thread tid = gate row j (0..255), 4 batches
            ull a0 = biasp1, a1 = biasp1, a2 = biasp1, a3 = biasp1;
            #pragma unroll
            for (int q = 0; q < 24; ++q) {
                const ulonglong2 w = *(const ulonglong2*)(sw1 + q * 1024 + tid * 4);
                ulonglong2 v;
                v = *(const ulonglong2*)(v1 + 0 * 96 + q * 4);
                a0 = fma2(w.x, v.x, a0); a0 = fma2(w.y, v.y, a0);
                v = *(const ulonglong2*)(v1 + 1 * 96 + q * 4);
                a1 = fma2(w.x, v.x, a1); a1 = fma2(w.y, v.y, a1);
                v = *(const ulonglong2*)(v1 + 2 * 96 + q * 4);
                a2 = fma2(w.x, v.x, a2); a2 = fma2(w.y, v.y, a2);
                v = *(const ulonglong2*)(v1 + 3 * 96 + q * 4);
                a3 = fma2(w.x, v.x, a3); a3 = fma2(w.y, v.y, a3);
            }
            g1[0 * 256 + tid] = hadd(a0);
            g1[1 * 256 + tid] = hadd(a1);
            g1[2 * 256 + tid] = hadd(a2);
            g1[3 * 256 + tid] = hadd(a3);
            __syncthreads();                       // S2: gates1 ready

            // ---- phase 2: LSTM1 state update (all 256 threads: b2_, n2_)
            {
                const float gi = g1[b2_ * 256 + n2_];
                const float gf = g1[b2_ * 256 + 64 + n2_];
                const float gg = g1[b2_ * 256 + 128 + n2_];
                const float go = g1[b2_ * 256 + 192 + n2_];
                const float ii = sigf(gi), ff = sigf(gf);
                const float g  = tanh_(gg), oo = sigf(go);
                c1s = ff * c1s + ii * g;
                const float h = oo * tanh_(c1s);
                v1[b2_ * 96 + 26 + n2_] = h;       // feeds LSTM1 recurrence
                v2[b2_ * 96 + n2_]      = h;       // feeds LSTM2 input
            }
            __syncthreads();                       // S3: h1 ready

            // ---- phase 3: LSTM2 gates. thread -> row jr_, batch pair p_
            ull e0 = biasp2, e1 = biasp2;
            const int bb0 = 2 * p_, bb1 = 2 * p_ + 1;
            #pragma unroll
            for (int q = 0; q < 24; ++q) {
                const ulonglong2 w = *(const ulonglong2*)(sw2 + q * 512 + jr_ * 4);
                ulonglong2 v;
                v = *(const ulonglong2*)(v2 + bb0 * 96 + q * 4);
                e0 = fma2(w.x, v.x, e0); e0 = fma2(w.y, v.y, e0);
                v = *(const ulonglong2*)(v2 + bb1 * 96 + q * 4);
                e1 = fma2(w.x, v.x, e1); e1 = fma2(w.y, v.y, e1);
            }
            g2[bb0 * 128 + jr_] = hadd(e0);
            g2[bb1 * 128 + jr_] = hadd(e1);
            __syncthreads();                       // S4: gates2 ready

            // ---- phase 4: LSTM2 state update (tid<128: b4_, n4_)
            if (tid < 128) {
                const float gi = g2[b4_ * 128 + n4_];
                const float gf = g2[b4_ * 128 + 32 + n4_];
                const float gg = g2[b4_ * 128 + 64 + n4_];
                const float go = g2[b4_ * 128 + 96 + n4_];
                const float ii = sigf(gi), ff = sigf(gf);
                const float g  = tanh_(gg), oo = sigf(go);
                c2s = ff * c2s + ii * g;
                v2[b4_ * 96 + 64 + n4_] = oo * tanh_(c2s);
            }
        }
    }
    __syncthreads();

    // ---- FC head on final h2 (v2[b][64..95])
    if (tid < 64) {
        const int b = tid >> 4, f = tid & 15;
        float a = __ldg(b_fc1 + f);
        #pragma unroll
        for (int k = 0; k < 32; ++k)
            a += __ldg(w_fc1 + f * 32 + k) * v2[b * 96 + 64 + k];
        fc1s[b * 16 + f] = fmaxf(a, 0.f);
    }
    __syncthreads();
    if (tid < 40) {
        const int b = tid / 10, o = tid - b * 10;
        float a = __ldg(b_fc2 + o);
        #pragma unroll
        for (int k = 0; k < 16; ++k)
            a += __ldg(w_fc2 + o * 16 + k) * fc1s[b * 16 + k];
        out[(b0 + b) * 10 + o] = a;
    }
}

extern "C" void kernel_launch(void* const* d_in, const int* in_sizes, int n_in,
                              void* d_out, int out_size) {
    (void)in_sizes; (void)n_in; (void)out_size;
    cudaFuncSetAttribute(audiolstm_kernel,
                         cudaFuncAttributeMaxDynamicSharedMemorySize, SMEM_BYTES);
    audiolstm_kernel<<<GRIDB, THREADS, SMEM_BYTES>>>(
        (const float*)d_in[0],
        (const float*)d_in[1], (const float*)d_in[2],
        (const float*)d_in[3], (const float*)d_in[4],
        (const float*)d_in[5], (const float*)d_in[6],
        (const float*)d_in[7], (const float*)d_in[8],
        (const float*)d_in[9], (const float*)d_in[10],
        (const float*)d_in[11], (const float*)d_in[12],
        (float*)d_out);
}